// round 7
// baseline (speedup 1.0000x reference)
#include <cuda_runtime.h>
#include <cuda_bf16.h>
#include <cstdint>

#define STRD 313
#define OFF_LS   0
#define OFF_RS   14976
#define OFF_COST 32256
#define OFF_P    93632
#define OFF_ENT  155008
#define OFF_PREV 156256
#define OFF_NEXT 157504
#define OFF_SEG  158752
#define OFF_RED  159936
#define SMEM_BYTES 160032

__device__ float g_row[256];

__device__ __forceinline__ int swz(int x) { return (x << 4) ^ ((x & 0x38) << 1); }

__device__ __forceinline__ void cp16(uint32_t dst, const void* src) {
    asm volatile("cp.async.cg.shared.global [%0], [%1], 16;\n" :: "r"(dst), "l"(src));
}

__device__ __forceinline__ float col_entropy(const float* cost, int x) {
    int dmax = x < 48 ? x : 48;
    const float* c = cost + x;
    float m = c[0];
    for (int d = 1; d <= dmax; d++) m = fmaxf(m, c[d * STRD]);
    float S = 0.f;
    for (int d = 0; d <= dmax; d++) S += expf((c[d * STRD] - m) * 10.0f);
    float logS = logf(S), invS = 1.0f / S;
    float thr = logS - 18.420681f;           // p >= 1e-8  <=>  l >= logS + ln(1e-8)
    float acc = 0.f;
    for (int d = 0; d <= dmax; d++) {
        float l = (c[d * STRD] - m) * 10.0f;
        if (l >= thr) { float p = expf(l) * invS; acc -= p * (l - logS); }
        else acc += 1.8420681e-7f;           // -EPS*log(EPS)
    }
    acc += (float)(48 - dmax) * 1.8420681e-7f;   // -inf (prob 0 -> clamp EPS) entries
    if (dmax == 0) return 0.f;                   // Deff == 1
    float e = acc / (logf((float)(dmax + 1)) + 1e-8f);
    return fminf(1.0f, fmaxf(0.0f, e));
}

__device__ __forceinline__ void extents(const float* ent, int* prevv, int* nextv, int tid) {
    int wid = tid >> 5, lane = tid & 31;
    if (wid == 0) {
        int carry = -1;
        for (int s = 0; s < 10; s++) {
            int idx = s * 32 + lane;
            int v = (idx < 312 && ent[idx] <= 0.6f) ? idx : -1;
            #pragma unroll
            for (int o = 1; o < 32; o <<= 1) {
                int t = __shfl_up_sync(0xffffffffu, v, o);
                if (lane >= o) v = max(v, t);
            }
            v = max(v, carry);
            if (idx < 312) prevv[idx] = v;
            carry = __shfl_sync(0xffffffffu, v, 31);
        }
    } else if (wid == 1) {
        int carry = 312;
        for (int s = 0; s < 10; s++) {
            int idx = 311 - (s * 32 + lane);
            int v = (idx >= 0 && ent[idx] <= 0.6f) ? idx : 312;
            #pragma unroll
            for (int o = 1; o < 32; o <<= 1) {
                int t = __shfl_up_sync(0xffffffffu, v, o);
                if (lane >= o) v = min(v, t);
            }
            v = min(v, carry);
            if (idx >= 0) nextv[idx] = v;
            carry = __shfl_sync(0xffffffffu, v, 31);
        }
    }
}

__device__ __forceinline__ void prefix_scan(const float* cost, float* P, float* segS, int tid) {
    int d = tid / 6, seg = tid - d * 6;
    if (tid < 294) {
        int xs = seg * 52;
        const float* c = cost + d * STRD;
        float* p = P + d * STRD;
        float s = 0.f;
        for (int x = xs; x < xs + 52; x++) { if (x >= d) s += c[x]; p[x] = s; }
        segS[tid] = s;
    }
    __syncthreads();
    if (tid < 294 && seg > 0) {
        float off = 0.f;
        for (int q = 0; q < seg; q++) off += segS[d * 6 + q];
        float* p = P + d * STRD;
        for (int x = seg * 52; x < seg * 52 + 52; x++) p[x] += off;
    }
    __syncthreads();
}

__device__ __forceinline__ void get_ab(const int* prevv, const int* nextv, int x, int& a, int& b) {
    int Lr = x - prevv[x] - 1; if (Lr < 0) Lr = 0;
    int Rr = nextv[x] - x - 1; if (Rr < 0) Rr = 0;
    a = x - Lr; if (a < x - 12) a = x - 12;   // x>=62 -> a>=50>0, no 0-clamp needed
    b = x + Rr; if (b > x + 12) b = x + 12;
    if (b > 311) b = 311;
}

__device__ __forceinline__ void issue_chunk(const float* Lrow, const float* Rrow,
                                            uint32_t sb, int tid, int k) {
    int buf = k % 3;
    if (tid < 312) {
        cp16(sb + OFF_LS + buf * 4992 + swz(tid),      Lrow + (size_t)tid * 384 + k * 4);
        cp16(sb + OFF_RS + buf * 5760 + swz(tid + 48), Rrow + (size_t)tid * 384 + k * 4);
    }
    asm volatile("cp.async.commit_group;\n" ::: "memory");
}

__global__ void __launch_bounds__(320, 1)
loss_row_kernel(const float* __restrict__ fL, const float* __restrict__ fR,
                const float* __restrict__ stu) {
    extern __shared__ __align__(128) char smem[];
    float* cost  = (float*)(smem + OFF_COST);
    float* P     = (float*)(smem + OFF_P);
    float* ent   = (float*)(smem + OFF_ENT);
    int*   prevv = (int*)(smem + OFF_PREV);
    int*   nextv = (int*)(smem + OFF_NEXT);
    float* segS  = (float*)(smem + OFF_SEG);
    float* redN  = (float*)(smem + OFF_RED);
    float* redC  = redN + 10;

    const int tid = threadIdx.x;
    const int row = blockIdx.x;
    const int b = row >> 5, h = 64 + (row & 31);
    const float* Lrow   = fL  + (size_t)(b * 96 + h) * (312 * 384);
    const float* Rrow   = fR  + (size_t)(b * 96 + h) * (312 * 384);
    const float* stuRow = stu + (size_t)(b * 96 + h) * 312;
    const uint32_t sb = (uint32_t)__cvta_generic_to_shared(smem);

    for (int t = tid; t < 3 * 48; t += 320) {  // zero R pads (x-d < 0)
        int buf = t / 48, j = t - buf * 48;
        *(float4*)(smem + OFF_RS + buf * 5760 + swz(j)) = make_float4(0.f, 0.f, 0.f, 0.f);
    }

    const int xg = tid / 7, dg = tid - xg * 7;
    const bool act = (tid < 273);              // 39 x-groups * 7 d-groups
    const int x0 = xg * 8, dbase = dg * 7;
    float acc[8][7];
    #pragma unroll
    for (int i = 0; i < 8; i++)
        #pragma unroll
        for (int dd = 0; dd < 7; dd++) acc[i][dd] = 0.f;

    issue_chunk(Lrow, Rrow, sb, tid, 0);
    issue_chunk(Lrow, Rrow, sb, tid, 1);
    issue_chunk(Lrow, Rrow, sb, tid, 2);

    for (int k = 0; k < 96; k++) {
        asm volatile("cp.async.wait_group 2;\n" ::: "memory");
        __syncthreads();
        if (act) {
            int buf = k % 3;
            float4 Lv[8], Rv[14];
            #pragma unroll
            for (int i = 0; i < 8; i++)
                Lv[i] = *(const float4*)(smem + OFF_LS + buf * 4992 + swz(x0 + i));
            int jb = x0 - dbase + 42;
            #pragma unroll
            for (int m = 0; m < 14; m++)
                Rv[m] = *(const float4*)(smem + OFF_RS + buf * 5760 + swz(jb + m));
            #pragma unroll
            for (int dd = 0; dd < 7; dd++)
                #pragma unroll
                for (int i = 0; i < 8; i++) {
                    float4 r = Rv[i - dd + 6];
                    float a = acc[i][dd];
                    a = fmaf(Lv[i].x, r.x, a);
                    a = fmaf(Lv[i].y, r.y, a);
                    a = fmaf(Lv[i].z, r.z, a);
                    a = fmaf(Lv[i].w, r.w, a);
                    acc[i][dd] = a;
                }
        }
        __syncthreads();
        if (k + 3 < 96) issue_chunk(Lrow, Rrow, sb, tid, k + 3);
    }

    if (act)
        #pragma unroll
        for (int i = 0; i < 8; i++)
            #pragma unroll
            for (int dd = 0; dd < 7; dd++)
                cost[(dbase + dd) * STRD + (x0 + i)] = acc[i][dd];  // x<d slots never read
    __syncthreads();

    // entropy ent0
    if (tid < 312) ent[tid] = col_entropy(cost, tid);
    __syncthreads();

    // stage-1: extents + prefix + refine + ent1
    extents(ent, prevv, nextv, tid);
    __syncthreads();
    prefix_scan(cost, P, segS, tid);
    if (tid < 157) {
        int x = 62 + tid;
        if (ent[x] > 0.6f) {
            int a, bb; get_ab(prevv, nextv, x, a, bb);
            float invd = 1.0f / (float)(bb - a + 1);  // window all-finite: a>=50>48>=d
            for (int d = 0; d <= 48; d++)
                cost[d * STRD + x] = (P[d * STRD + bb] - P[d * STRD + a - 1]) * invd;
            ent[x] = col_entropy(cost, x);  // own column only, no cross-thread reads
        }
    }
    __syncthreads();

    // stage-2: extents + prefix + teacher + loss
    extents(ent, prevv, nextv, tid);
    __syncthreads();
    prefix_scan(cost, P, segS, tid);

    float lnum = 0.f, lcnt = 0.f;
    if (tid < 157) {
        int x = 62 + tid;
        if (ent[x] > 0.6f) {   // rm2
            int a, bb; get_ab(prevv, nextv, x, a, bb);
            float best = -3.4e38f; int bd = 0;
            for (int d = 0; d <= 48; d++) {   // argmax of window-sum == argmax of mean
                float nm = P[d * STRD + bb] - P[d * STRD + a - 1];
                if (nm > best) { best = nm; bd = d; }
            }
            float ad = fabsf(stuRow[x] * 0.25f - (float)bd);
            lnum = (ad < 1.f) ? 0.5f * ad * ad : ad - 0.5f;
            lcnt = 1.f;
        }
    }
    int wid = tid >> 5, lane = tid & 31;
    #pragma unroll
    for (int o = 16; o; o >>= 1) {
        lnum += __shfl_down_sync(0xffffffffu, lnum, o);
        lcnt += __shfl_down_sync(0xffffffffu, lcnt, o);
    }
    if (lane == 0) { redN[wid] = lnum; redC[wid] = lcnt; }
    __syncthreads();
    if (tid == 0) {
        float n = 0.f, c = 0.f;
        for (int w = 0; w < 10; w++) { n += redN[w]; c += redC[w]; }
        g_row[row * 2] = n; g_row[row * 2 + 1] = c;
    }
}

__global__ void finalize_kernel(float* out) {
    int t = threadIdx.x;
    float acc = 0.f;
    if (t < 4) {
        float n = 0.f, c = 0.f;
        for (int r = t * 32; r < t * 32 + 32; r++) { n += g_row[2 * r]; c += g_row[2 * r + 1]; }
        acc = n / fmaxf(c, 1.f);
    }
    acc += __shfl_down_sync(0xffffffffu, acc, 2);
    acc += __shfl_down_sync(0xffffffffu, acc, 1);
    if (t == 0) out[0] = acc * 0.25f;
}

extern "C" void kernel_launch(void* const* d_in, const int* in_sizes, int n_in,
                              void* d_out, int out_size) {
    const float* fL  = (const float*)d_in[0];
    const float* fR  = (const float*)d_in[1];
    const float* stu = (const float*)d_in[2];
    cudaFuncSetAttribute(loss_row_kernel, cudaFuncAttributeMaxDynamicSharedMemorySize, SMEM_BYTES);
    loss_row_kernel<<<128, 320, SMEM_BYTES>>>(fL, fR, stu);
    finalize_kernel<<<1, 32>>>((float*)d_out);
}